// round 13
// baseline (speedup 1.0000x reference)
#include <cuda_runtime.h>
#include <math.h>

#define NCLS 6
#define TT 60
#define NBLK 192   // 3 scales * 64 batches

// per-block partials: [cls_sum, iou_sum, inner_sum, npos] — fully rewritten every call
__device__ float g_part[NBLK * 4];
__device__ unsigned int g_count = 0;   // arrival counter; last block resets to 0

__device__ __forceinline__ float bce_f(float x, float t) {
    return fmaxf(x, 0.0f) - x * t + log1pf(expf(-fabsf(x)));
}

__device__ __forceinline__ float iou_f(float px, float py, float pw, float ph,
                                       float tx, float ty, float tw, float th) {
    float x11 = px - pw * 0.5f, y11 = py - ph * 0.5f;
    float x12 = px + pw * 0.5f, y12 = py + ph * 0.5f;
    float x21 = tx - tw * 0.5f, y21 = ty - th * 0.5f;
    float x22 = tx + tw * 0.5f, y22 = ty + th * 0.5f;
    float iw = fmaxf(fminf(x12, x22) - fmaxf(x11, x21), 0.0f);
    float ih = fmaxf(fminf(y12, y22) - fmaxf(y11, y21), 0.0f);
    float inter = iw * ih;
    float a1 = (x12 - x11) * (y12 - y11);
    float a2 = (x22 - x21) * (y22 - y21);
    return inter / (a1 + a2 - inter + 1e-7f);
}

__global__ void __launch_bounds__(64)
det_loss_fused(const float* __restrict__ p3,
               const float* __restrict__ p4,
               const float* __restrict__ p5,
               const int*   __restrict__ tcls,
               const float* __restrict__ tbox,
               float* __restrict__ out) {
    const int bx = blockIdx.x;
    const int scale = bx >> 6;        // 0,1,2
    const int b = bx & 63;
    const int W = 160 >> scale;       // H == W
    const float* __restrict__ pred = (scale == 0) ? p3 : ((scale == 1) ? p4 : p5);

    __shared__ int scell[TT];
    __shared__ unsigned char sclsid[TT];

    const int t = threadIdx.x;

    // Load this thread's target box early (coalesced float4)
    float txv = 0.f, tyv = 0.f, twv = 0.f, thv = 0.f;
    if (t < TT) {
        const float4 tb = ((const float4*)tbox)[(size_t)b * TT + t];
        txv = tb.x; tyv = tb.y; twv = tb.z; thv = tb.w;
        int gx = (int)(txv * (float)W);  gx = min(max(gx, 0), W - 1);
        int gy = (int)(tyv * (float)W);  gy = min(max(gy, 0), W - 1);
        scell[t]  = gy * W + gx;
        sclsid[t] = (unsigned char)tcls[b * TT + t];
    }
    __syncthreads();

    float cls_sum = 0.0f, iou_sum = 0.0f, inner_sum = 0.0f, npos = 0.0f;

    if (t < TT) {
        const int mycell = scell[t];

        // ── speculative gather: start the 10 scattered DRAM loads NOW so their
        //    latency overlaps the collision scan below ──
        const int gy0 = mycell / W;
        const int gx0 = mycell - gy0 * W;
        const size_t HW  = (size_t)W * (size_t)W;
        const size_t off = (size_t)(b * 11) * HW + (size_t)gy0 * W + gx0;
        float cpred[NCLS];
        #pragma unroll
        for (int c = 0; c < NCLS; c++) cpred[c] = pred[off + (size_t)c * HW];
        const float px = pred[off + (size_t)7  * HW];
        const float py = pred[off + (size_t)8  * HW];
        const float pw = pred[off + (size_t)9  * HW];
        const float ph = pred[off + (size_t)10 * HW];

        // ── collision scan (smem): last (highest t) target wins the cell;
        //    cls target is OR of class bits over co-located targets ──
        unsigned mask = 0u;
        bool winner = true;
        #pragma unroll
        for (int j = 0; j < TT; j++) {
            if (scell[j] == mycell) {
                mask |= 1u << sclsid[j];
                if (j > t) winner = false;
            }
        }

        if (winner) {
            #pragma unroll
            for (int c = 0; c < NCLS; c++) {
                const float tv = ((mask >> c) & 1u) ? 1.0f : 0.0f;
                cls_sum += bce_f(cpred[c], tv);
            }
            const float iou   = iou_f(px, py, pw, ph, txv, tyv, twv, thv);
            const float inner = iou_f(px, py, pw * 0.7f, ph * 0.7f,
                                      txv, tyv, twv * 0.7f, thv * 0.7f);
            iou_sum   = 1.0f - iou;
            inner_sum = 1.0f - inner;
            npos      = 1.0f;
        }
    }

    // block reduce over 64 threads (2 warps) — all lanes participate
    const unsigned fullm = 0xFFFFFFFFu;
    #pragma unroll
    for (int s = 16; s > 0; s >>= 1) {
        cls_sum   += __shfl_down_sync(fullm, cls_sum,   s);
        iou_sum   += __shfl_down_sync(fullm, iou_sum,   s);
        inner_sum += __shfl_down_sync(fullm, inner_sum, s);
        npos      += __shfl_down_sync(fullm, npos,      s);
    }
    __shared__ float red[2][4];
    __shared__ bool s_is_last;
    const int wid = t >> 5, lid = t & 31;
    if (lid == 0) {
        red[wid][0] = cls_sum; red[wid][1] = iou_sum;
        red[wid][2] = inner_sum; red[wid][3] = npos;
    }
    __syncthreads();
    if (t == 0) {
        g_part[bx * 4 + 0] = red[0][0] + red[1][0];
        g_part[bx * 4 + 1] = red[0][1] + red[1][1];
        g_part[bx * 4 + 2] = red[0][2] + red[1][2];
        g_part[bx * 4 + 3] = red[0][3] + red[1][3];
        __threadfence();                       // publish partials before arrival
        const unsigned prev = atomicAdd(&g_count, 1u);
        s_is_last = (prev == NBLK - 1u);
    }
    __syncthreads();

    if (!s_is_last) return;

    // ── last block: acquire, then vectorized (LDG.128) fixed-order tail ──
    __threadfence();                           // acquire: partials now visible
    __shared__ float sums[12];
    if (t < 12) {
        const int s = t >> 2, k = t & 3;       // scale, component
        const float4* gp4 = (const float4*)&g_part[(s * 64) * 4];
        // 16 float4 loads per thread (vs 64 scalar); keep k-component of each
        // quad group-of-4 so the per-k addend order matches the prior kernel:
        // a0: blocks i*4+0, a1: i*4+1, a2: i*4+2, a3: i*4+3
        float a0 = 0.0f, a1 = 0.0f, a2 = 0.0f, a3 = 0.0f;
        #pragma unroll
        for (int i = 0; i < 16; i++) {
            const float4 q0 = gp4[i * 4 + 0];
            const float4 q1 = gp4[i * 4 + 1];
            const float4 q2 = gp4[i * 4 + 2];
            const float4 q3 = gp4[i * 4 + 3];
            const float v0 = (k == 0) ? q0.x : (k == 1) ? q0.y : (k == 2) ? q0.z : q0.w;
            const float v1 = (k == 0) ? q1.x : (k == 1) ? q1.y : (k == 2) ? q1.z : q1.w;
            const float v2 = (k == 0) ? q2.x : (k == 1) ? q2.y : (k == 2) ? q2.z : q2.w;
            const float v3 = (k == 0) ? q3.x : (k == 1) ? q3.y : (k == 2) ? q3.z : q3.w;
            a0 += v0; a1 += v1; a2 += v2; a3 += v3;
        }
        sums[t] = (a0 + a1) + (a2 + a3);
    }
    __syncthreads();

    if (t == 0) {
        float cls_total = 0.0f, box_total = 0.0f;
        #pragma unroll
        for (int s2 = 0; s2 < 3; s2++) {
            const float np        = sums[s2 * 4 + 3];
            const float denom     = np + 1e-8f;
            const float cls_loss  = sums[s2 * 4 + 0] / denom;
            const float iou_term  = sums[s2 * 4 + 1] / denom;
            const float inner_t   = sums[s2 * 4 + 2] / denom;
            const float inner_iou = 0.5f * iou_term + 0.5f * inner_t;  // (1-INNER_W), INNER_W
            const float box_loss  = 0.5f * iou_term + 0.5f * inner_iou;
            cls_total += cls_loss;
            box_total += box_loss;
        }
        cls_total = cls_total / 3.0f;
        box_total = box_total / 3.0f;
        const float total = 0.5f * cls_total + 7.5f * box_total;
        out[0] = total;
        out[1] = cls_total;
        out[2] = box_total;
        g_count = 0;   // reset for next (graph-replayed) launch
    }
}

extern "C" void kernel_launch(void* const* d_in, const int* in_sizes, int n_in,
                              void* d_out, int out_size) {
    const float* p3   = (const float*)d_in[0];
    const float* p4   = (const float*)d_in[1];
    const float* p5   = (const float*)d_in[2];
    const int*   tcls = (const int*)  d_in[3];
    const float* tbox = (const float*)d_in[4];
    float* out = (float*)d_out;

    det_loss_fused<<<NBLK, 64>>>(p3, p4, p5, tcls, tbox, out);
}

// round 14
// speedup vs baseline: 1.3801x; 1.3801x over previous
#include <cuda_runtime.h>
#include <math.h>

#define NCLS 6
#define TT 60
#define NBLK 192   // 3 scales * 64 batches

// per-block partials: [cls_sum, iou_sum, inner_sum, npos] — fully rewritten every call
__device__ float g_part[NBLK * 4];
__device__ unsigned int g_count = 0;   // arrival counter; last block resets to 0

__device__ __forceinline__ float bce_f(float x, float t) {
    return fmaxf(x, 0.0f) - x * t + log1pf(expf(-fabsf(x)));
}

__device__ __forceinline__ float iou_f(float px, float py, float pw, float ph,
                                       float tx, float ty, float tw, float th) {
    float x11 = px - pw * 0.5f, y11 = py - ph * 0.5f;
    float x12 = px + pw * 0.5f, y12 = py + ph * 0.5f;
    float x21 = tx - tw * 0.5f, y21 = ty - th * 0.5f;
    float x22 = tx + tw * 0.5f, y22 = ty + th * 0.5f;
    float iw = fmaxf(fminf(x12, x22) - fmaxf(x11, x21), 0.0f);
    float ih = fmaxf(fminf(y12, y22) - fmaxf(y11, y21), 0.0f);
    float inter = iw * ih;
    float a1 = (x12 - x11) * (y12 - y11);
    float a2 = (x22 - x21) * (y22 - y21);
    return inter / (a1 + a2 - inter + 1e-7f);
}

__global__ void __launch_bounds__(64)
det_loss_fused(const float* __restrict__ p3,
               const float* __restrict__ p4,
               const float* __restrict__ p5,
               const int*   __restrict__ tcls,
               const float* __restrict__ tbox,
               float* __restrict__ out) {
    const int bx = blockIdx.x;
    const int scale = bx >> 6;        // 0,1,2
    const int b = bx & 63;
    const int W = 160 >> scale;       // H == W
    const float* __restrict__ pred = (scale == 0) ? p3 : ((scale == 1) ? p4 : p5);

    __shared__ int scell[TT];
    __shared__ unsigned char sclsid[TT];

    const int t = threadIdx.x;

    // Load this thread's target box early (coalesced float4)
    float txv = 0.f, tyv = 0.f, twv = 0.f, thv = 0.f;
    if (t < TT) {
        const float4 tb = ((const float4*)tbox)[(size_t)b * TT + t];
        txv = tb.x; tyv = tb.y; twv = tb.z; thv = tb.w;
        int gx = (int)(txv * (float)W);  gx = min(max(gx, 0), W - 1);
        int gy = (int)(tyv * (float)W);  gy = min(max(gy, 0), W - 1);
        scell[t]  = gy * W + gx;
        sclsid[t] = (unsigned char)tcls[b * TT + t];
    }
    __syncthreads();

    float cls_sum = 0.0f, iou_sum = 0.0f, inner_sum = 0.0f, npos = 0.0f;

    if (t < TT) {
        const int mycell = scell[t];

        // ── speculative gather: start the 10 scattered DRAM loads NOW so their
        //    latency overlaps the collision scan below ──
        const int gy0 = mycell / W;
        const int gx0 = mycell - gy0 * W;
        const size_t HW  = (size_t)W * (size_t)W;
        const size_t off = (size_t)(b * 11) * HW + (size_t)gy0 * W + gx0;
        float cpred[NCLS];
        #pragma unroll
        for (int c = 0; c < NCLS; c++) cpred[c] = pred[off + (size_t)c * HW];
        const float px = pred[off + (size_t)7  * HW];
        const float py = pred[off + (size_t)8  * HW];
        const float pw = pred[off + (size_t)9  * HW];
        const float ph = pred[off + (size_t)10 * HW];

        // ── collision scan (smem): last (highest t) target wins the cell;
        //    cls target is OR of class bits over co-located targets ──
        unsigned mask = 0u;
        bool winner = true;
        #pragma unroll
        for (int j = 0; j < TT; j++) {
            if (scell[j] == mycell) {
                mask |= 1u << sclsid[j];
                if (j > t) winner = false;
            }
        }

        if (winner) {
            #pragma unroll
            for (int c = 0; c < NCLS; c++) {
                const float tv = ((mask >> c) & 1u) ? 1.0f : 0.0f;
                cls_sum += bce_f(cpred[c], tv);
            }
            const float iou   = iou_f(px, py, pw, ph, txv, tyv, twv, thv);
            const float inner = iou_f(px, py, pw * 0.7f, ph * 0.7f,
                                      txv, tyv, twv * 0.7f, thv * 0.7f);
            iou_sum   = 1.0f - iou;
            inner_sum = 1.0f - inner;
            npos      = 1.0f;
        }
    }

    // block reduce over 64 threads (2 warps) — all lanes participate
    const unsigned fullm = 0xFFFFFFFFu;
    #pragma unroll
    for (int s = 16; s > 0; s >>= 1) {
        cls_sum   += __shfl_down_sync(fullm, cls_sum,   s);
        iou_sum   += __shfl_down_sync(fullm, iou_sum,   s);
        inner_sum += __shfl_down_sync(fullm, inner_sum, s);
        npos      += __shfl_down_sync(fullm, npos,      s);
    }
    __shared__ float red[2][4];
    __shared__ bool s_is_last;
    const int wid = t >> 5, lid = t & 31;
    if (lid == 0) {
        red[wid][0] = cls_sum; red[wid][1] = iou_sum;
        red[wid][2] = inner_sum; red[wid][3] = npos;
    }
    __syncthreads();
    if (t == 0) {
        g_part[bx * 4 + 0] = red[0][0] + red[1][0];
        g_part[bx * 4 + 1] = red[0][1] + red[1][1];
        g_part[bx * 4 + 2] = red[0][2] + red[1][2];
        g_part[bx * 4 + 3] = red[0][3] + red[1][3];
        __threadfence();                       // publish partials before arrival
        const unsigned prev = atomicAdd(&g_count, 1u);
        s_is_last = (prev == NBLK - 1u);
    }
    __syncthreads();

    if (!s_is_last) return;

    // ── last block: acquire, then PLAIN (batchable) loads; fixed-order sum ──
    __threadfence();                           // acquire: partials now visible
    __shared__ float sums[12];
    if (t < 12) {
        const int s = t >> 2, k = t & 3;
        float a0 = 0.0f, a1 = 0.0f, a2 = 0.0f, a3 = 0.0f;
        const int base = (s * 64) * 4 + k;
        #pragma unroll
        for (int i = 0; i < 16; i++) {
            a0 += g_part[base + (i * 4 + 0) * 4];
            a1 += g_part[base + (i * 4 + 1) * 4];
            a2 += g_part[base + (i * 4 + 2) * 4];
            a3 += g_part[base + (i * 4 + 3) * 4];
        }
        sums[t] = (a0 + a1) + (a2 + a3);
    }
    __syncthreads();

    if (t == 0) {
        float cls_total = 0.0f, box_total = 0.0f;
        #pragma unroll
        for (int s2 = 0; s2 < 3; s2++) {
            const float np        = sums[s2 * 4 + 3];
            const float denom     = np + 1e-8f;
            const float cls_loss  = sums[s2 * 4 + 0] / denom;
            const float iou_term  = sums[s2 * 4 + 1] / denom;
            const float inner_t   = sums[s2 * 4 + 2] / denom;
            const float inner_iou = 0.5f * iou_term + 0.5f * inner_t;  // (1-INNER_W), INNER_W
            const float box_loss  = 0.5f * iou_term + 0.5f * inner_iou;
            cls_total += cls_loss;
            box_total += box_loss;
        }
        cls_total = cls_total / 3.0f;
        box_total = box_total / 3.0f;
        const float total = 0.5f * cls_total + 7.5f * box_total;
        out[0] = total;
        out[1] = cls_total;
        out[2] = box_total;
        g_count = 0;   // reset for next (graph-replayed) launch
    }
}

extern "C" void kernel_launch(void* const* d_in, const int* in_sizes, int n_in,
                              void* d_out, int out_size) {
    const float* p3   = (const float*)d_in[0];
    const float* p4   = (const float*)d_in[1];
    const float* p5   = (const float*)d_in[2];
    const int*   tcls = (const int*)  d_in[3];
    const float* tbox = (const float*)d_in[4];
    float* out = (float*)d_out;

    det_loss_fused<<<NBLK, 64>>>(p3, p4, p5, tcls, tbox, out);
}

// round 15
// speedup vs baseline: 1.5032x; 1.0892x over previous
#include <cuda_runtime.h>
#include <math.h>

#define NCLS 6
#define TT 60
#define NBLK 192   // 3 scales * 64 batches

// 12 accumulators, EACH padded to its own 128B L2 line (no same-line atomic
// serialization — the R9/R10 mistake). [scale*4 + k], k={cls,iou,inner,npos}
struct __align__(128) PaddedAcc { float v; float pad[31]; };
__device__ PaddedAcc g_acc[12];
__device__ __align__(128) unsigned int g_count = 0;  // own line; last block resets

__device__ __forceinline__ float bce_f(float x, float t) {
    return fmaxf(x, 0.0f) - x * t + log1pf(expf(-fabsf(x)));
}

__device__ __forceinline__ float iou_f(float px, float py, float pw, float ph,
                                       float tx, float ty, float tw, float th) {
    float x11 = px - pw * 0.5f, y11 = py - ph * 0.5f;
    float x12 = px + pw * 0.5f, y12 = py + ph * 0.5f;
    float x21 = tx - tw * 0.5f, y21 = ty - th * 0.5f;
    float x22 = tx + tw * 0.5f, y22 = ty + th * 0.5f;
    float iw = fmaxf(fminf(x12, x22) - fmaxf(x11, x21), 0.0f);
    float ih = fmaxf(fminf(y12, y22) - fmaxf(y11, y21), 0.0f);
    float inter = iw * ih;
    float a1 = (x12 - x11) * (y12 - y11);
    float a2 = (x22 - x21) * (y22 - y21);
    return inter / (a1 + a2 - inter + 1e-7f);
}

// acq_rel fetch-add: release orders this block's value-atomics before the
// arrival; acquire on the 192nd arrival makes all accumulators visible.
__device__ __forceinline__ unsigned int arrive_acq_rel(unsigned int* p) {
    unsigned int old;
    asm volatile("atom.acq_rel.gpu.global.add.u32 %0, [%1], 1;"
                 : "=r"(old) : "l"(p) : "memory");
    return old;
}

__global__ void __launch_bounds__(64)
det_loss_fused(const float* __restrict__ p3,
               const float* __restrict__ p4,
               const float* __restrict__ p5,
               const int*   __restrict__ tcls,
               const float* __restrict__ tbox,
               float* __restrict__ out) {
    const int bx = blockIdx.x;
    const int scale = bx >> 6;        // 0,1,2
    const int b = bx & 63;
    const int W = 160 >> scale;       // H == W
    const float* __restrict__ pred = (scale == 0) ? p3 : ((scale == 1) ? p4 : p5);

    __shared__ int scell[TT];
    __shared__ unsigned char sclsid[TT];

    const int t = threadIdx.x;

    // Load this thread's target box early (coalesced float4)
    float txv = 0.f, tyv = 0.f, twv = 0.f, thv = 0.f;
    if (t < TT) {
        const float4 tb = ((const float4*)tbox)[(size_t)b * TT + t];
        txv = tb.x; tyv = tb.y; twv = tb.z; thv = tb.w;
        int gx = (int)(txv * (float)W);  gx = min(max(gx, 0), W - 1);
        int gy = (int)(tyv * (float)W);  gy = min(max(gy, 0), W - 1);
        scell[t]  = gy * W + gx;
        sclsid[t] = (unsigned char)tcls[b * TT + t];
    }
    __syncthreads();

    float cls_sum = 0.0f, iou_sum = 0.0f, inner_sum = 0.0f, npos = 0.0f;

    if (t < TT) {
        const int mycell = scell[t];

        // ── speculative gather: start the 10 scattered DRAM loads NOW so their
        //    latency overlaps the collision scan below ──
        const int gy0 = mycell / W;
        const int gx0 = mycell - gy0 * W;
        const size_t HW  = (size_t)W * (size_t)W;
        const size_t off = (size_t)(b * 11) * HW + (size_t)gy0 * W + gx0;
        float cpred[NCLS];
        #pragma unroll
        for (int c = 0; c < NCLS; c++) cpred[c] = pred[off + (size_t)c * HW];
        const float px = pred[off + (size_t)7  * HW];
        const float py = pred[off + (size_t)8  * HW];
        const float pw = pred[off + (size_t)9  * HW];
        const float ph = pred[off + (size_t)10 * HW];

        // ── collision scan (smem): last (highest t) target wins the cell;
        //    cls target is OR of class bits over co-located targets ──
        unsigned mask = 0u;
        bool winner = true;
        #pragma unroll
        for (int j = 0; j < TT; j++) {
            if (scell[j] == mycell) {
                mask |= 1u << sclsid[j];
                if (j > t) winner = false;
            }
        }

        if (winner) {
            #pragma unroll
            for (int c = 0; c < NCLS; c++) {
                const float tv = ((mask >> c) & 1u) ? 1.0f : 0.0f;
                cls_sum += bce_f(cpred[c], tv);
            }
            const float iou   = iou_f(px, py, pw, ph, txv, tyv, twv, thv);
            const float inner = iou_f(px, py, pw * 0.7f, ph * 0.7f,
                                      txv, tyv, twv * 0.7f, thv * 0.7f);
            iou_sum   = 1.0f - iou;
            inner_sum = 1.0f - inner;
            npos      = 1.0f;
        }
    }

    // block reduce over 64 threads (2 warps) — all lanes participate
    const unsigned fullm = 0xFFFFFFFFu;
    #pragma unroll
    for (int s = 16; s > 0; s >>= 1) {
        cls_sum   += __shfl_down_sync(fullm, cls_sum,   s);
        iou_sum   += __shfl_down_sync(fullm, iou_sum,   s);
        inner_sum += __shfl_down_sync(fullm, inner_sum, s);
        npos      += __shfl_down_sync(fullm, npos,      s);
    }
    __shared__ float red[2][4];
    __shared__ bool s_is_last;
    const int wid = t >> 5, lid = t & 31;
    if (lid == 0) {
        red[wid][0] = cls_sum; red[wid][1] = iou_sum;
        red[wid][2] = inner_sum; red[wid][3] = npos;
    }
    __syncthreads();

    // t0 publishes via 4 value-atomics to 4 DISTINCT padded lines, then acq_rel
    // arrival (no membar). Per-line contention: only 64 ops across the grid.
    if (t == 0) {
        const int base = scale * 4;
        atomicAdd(&g_acc[base + 0].v, red[0][0] + red[1][0]);
        atomicAdd(&g_acc[base + 1].v, red[0][1] + red[1][1]);
        atomicAdd(&g_acc[base + 2].v, red[0][2] + red[1][2]);
        atomicAdd(&g_acc[base + 3].v, red[0][3] + red[1][3]);
        const unsigned prev = arrive_acq_rel(&g_count);
        s_is_last = (prev == NBLK - 1u);
    }
    __syncthreads();

    if (!s_is_last) return;

    // ── last block, t0 only: 12 loads (one RTT), finish, reset ──
    if (t == 0) {
        float sums[12];
        #pragma unroll
        for (int i = 0; i < 12; i++) sums[i] = __ldcg(&g_acc[i].v);

        float cls_total = 0.0f, box_total = 0.0f;
        #pragma unroll
        for (int s2 = 0; s2 < 3; s2++) {
            const float np        = sums[s2 * 4 + 3];
            const float denom     = np + 1e-8f;
            const float cls_loss  = sums[s2 * 4 + 0] / denom;
            const float iou_term  = sums[s2 * 4 + 1] / denom;
            const float inner_t   = sums[s2 * 4 + 2] / denom;
            const float inner_iou = 0.5f * iou_term + 0.5f * inner_t;  // (1-INNER_W), INNER_W
            const float box_loss  = 0.5f * iou_term + 0.5f * inner_iou;
            cls_total += cls_loss;
            box_total += box_loss;
        }
        cls_total = cls_total / 3.0f;
        box_total = box_total / 3.0f;
        const float total = 0.5f * cls_total + 7.5f * box_total;
        out[0] = total;
        out[1] = cls_total;
        out[2] = box_total;

        // reset for next graph replay (same thread -> ordered; visible at kernel end)
        #pragma unroll
        for (int i = 0; i < 12; i++) g_acc[i].v = 0.0f;
        __threadfence();
        g_count = 0;
    }
}

extern "C" void kernel_launch(void* const* d_in, const int* in_sizes, int n_in,
                              void* d_out, int out_size) {
    const float* p3   = (const float*)d_in[0];
    const float* p4   = (const float*)d_in[1];
    const float* p5   = (const float*)d_in[2];
    const int*   tcls = (const int*)  d_in[3];
    const float* tbox = (const float*)d_in[4];
    float* out = (float*)d_out;

    det_loss_fused<<<NBLK, 64>>>(p3, p4, p5, tcls, tbox, out);
}

// round 16
// speedup vs baseline: 1.6857x; 1.1214x over previous
#include <cuda_runtime.h>
#include <math.h>

#define NCLS 6
#define TT 60
#define NBLK 192   // 3 scales * 64 batches

// 12 accumulators, EACH padded to its own 128B L2 line (no same-line atomic
// serialization). [scale*4 + k], k={cls,iou,inner,npos}
struct __align__(128) PaddedAcc { float v; float pad[31]; };
__device__ PaddedAcc g_acc[12];
__device__ __align__(128) unsigned int g_count = 0;  // own line; last block resets

__device__ __forceinline__ float bce_f(float x, float t) {
    return fmaxf(x, 0.0f) - x * t + log1pf(expf(-fabsf(x)));
}

__device__ __forceinline__ float iou_f(float px, float py, float pw, float ph,
                                       float tx, float ty, float tw, float th) {
    float x11 = px - pw * 0.5f, y11 = py - ph * 0.5f;
    float x12 = px + pw * 0.5f, y12 = py + ph * 0.5f;
    float x21 = tx - tw * 0.5f, y21 = ty - th * 0.5f;
    float x22 = tx + tw * 0.5f, y22 = ty + th * 0.5f;
    float iw = fmaxf(fminf(x12, x22) - fmaxf(x11, x21), 0.0f);
    float ih = fmaxf(fminf(y12, y22) - fmaxf(y11, y21), 0.0f);
    float inter = iw * ih;
    float a1 = (x12 - x11) * (y12 - y11);
    float a2 = (x22 - x21) * (y22 - y21);
    return inter / (a1 + a2 - inter + 1e-7f);
}

// acq_rel fetch-add: release orders this block's value-atomics before the
// arrival; acquire on the 192nd arrival makes all accumulators visible.
__device__ __forceinline__ unsigned int arrive_acq_rel(unsigned int* p) {
    unsigned int old;
    asm volatile("atom.acq_rel.gpu.global.add.u32 %0, [%1], 1;"
                 : "=r"(old) : "l"(p) : "memory");
    return old;
}

__global__ void __launch_bounds__(64)
det_loss_fused(const float* __restrict__ p3,
               const float* __restrict__ p4,
               const float* __restrict__ p5,
               const int*   __restrict__ tcls,
               const float* __restrict__ tbox,
               float* __restrict__ out) {
    const int bx = blockIdx.x;
    const int scale = bx >> 6;        // 0,1,2
    const int b = bx & 63;
    const int W = 160 >> scale;       // H == W
    const float* __restrict__ pred = (scale == 0) ? p3 : ((scale == 1) ? p4 : p5);

    __shared__ int scell[TT];
    __shared__ unsigned char sclsid[TT];

    const int t = threadIdx.x;

    // Load this thread's target box early (coalesced float4)
    float txv = 0.f, tyv = 0.f, twv = 0.f, thv = 0.f;
    if (t < TT) {
        const float4 tb = ((const float4*)tbox)[(size_t)b * TT + t];
        txv = tb.x; tyv = tb.y; twv = tb.z; thv = tb.w;
        int gx = (int)(txv * (float)W);  gx = min(max(gx, 0), W - 1);
        int gy = (int)(tyv * (float)W);  gy = min(max(gy, 0), W - 1);
        scell[t]  = gy * W + gx;
        sclsid[t] = (unsigned char)tcls[b * TT + t];
    }
    __syncthreads();

    float cls_sum = 0.0f, iou_sum = 0.0f, inner_sum = 0.0f, npos = 0.0f;

    if (t < TT) {
        const int mycell = scell[t];

        // ── speculative gather: start the 10 scattered DRAM loads NOW so their
        //    latency overlaps the collision scan below ──
        const int gy0 = mycell / W;
        const int gx0 = mycell - gy0 * W;
        const size_t HW  = (size_t)W * (size_t)W;
        const size_t off = (size_t)(b * 11) * HW + (size_t)gy0 * W + gx0;
        float cpred[NCLS];
        #pragma unroll
        for (int c = 0; c < NCLS; c++) cpred[c] = pred[off + (size_t)c * HW];
        const float px = pred[off + (size_t)7  * HW];
        const float py = pred[off + (size_t)8  * HW];
        const float pw = pred[off + (size_t)9  * HW];
        const float ph = pred[off + (size_t)10 * HW];

        // ── collision scan (smem): last (highest t) target wins the cell;
        //    cls target is OR of class bits over co-located targets ──
        unsigned mask = 0u;
        bool winner = true;
        #pragma unroll
        for (int j = 0; j < TT; j++) {
            if (scell[j] == mycell) {
                mask |= 1u << sclsid[j];
                if (j > t) winner = false;
            }
        }

        if (winner) {
            #pragma unroll
            for (int c = 0; c < NCLS; c++) {
                const float tv = ((mask >> c) & 1u) ? 1.0f : 0.0f;
                cls_sum += bce_f(cpred[c], tv);
            }
            const float iou   = iou_f(px, py, pw, ph, txv, tyv, twv, thv);
            const float inner = iou_f(px, py, pw * 0.7f, ph * 0.7f,
                                      txv, tyv, twv * 0.7f, thv * 0.7f);
            iou_sum   = 1.0f - iou;
            inner_sum = 1.0f - inner;
            npos      = 1.0f;
        }
    }

    // block reduce over 64 threads (2 warps) — all lanes participate
    const unsigned fullm = 0xFFFFFFFFu;
    #pragma unroll
    for (int s = 16; s > 0; s >>= 1) {
        cls_sum   += __shfl_down_sync(fullm, cls_sum,   s);
        iou_sum   += __shfl_down_sync(fullm, iou_sum,   s);
        inner_sum += __shfl_down_sync(fullm, inner_sum, s);
        npos      += __shfl_down_sync(fullm, npos,      s);
    }
    __shared__ float red[2][4];
    const int wid = t >> 5, lid = t & 31;
    if (lid == 0) {
        red[wid][0] = cls_sum; red[wid][1] = iou_sum;
        red[wid][2] = inner_sum; red[wid][3] = npos;
    }
    __syncthreads();

    // Tail is t0-only — every other thread exits now (no barrier, no broadcast).
    if (t != 0) return;

    // publish via 4 value-atomics to 4 DISTINCT padded lines, then acq_rel arrival
    const int base = scale * 4;
    atomicAdd(&g_acc[base + 0].v, red[0][0] + red[1][0]);
    atomicAdd(&g_acc[base + 1].v, red[0][1] + red[1][1]);
    atomicAdd(&g_acc[base + 2].v, red[0][2] + red[1][2]);
    atomicAdd(&g_acc[base + 3].v, red[0][3] + red[1][3]);
    const unsigned prev = arrive_acq_rel(&g_count);
    if (prev != NBLK - 1u) return;

    // ── last arrival (t0 of the final block): 12 loads, finish, reset ──
    float sums[12];
    #pragma unroll
    for (int i = 0; i < 12; i++) sums[i] = __ldcg(&g_acc[i].v);

    float cls_total = 0.0f, box_total = 0.0f;
    #pragma unroll
    for (int s2 = 0; s2 < 3; s2++) {
        const float np        = sums[s2 * 4 + 3];
        const float denom     = np + 1e-8f;
        const float cls_loss  = sums[s2 * 4 + 0] / denom;
        const float iou_term  = sums[s2 * 4 + 1] / denom;
        const float inner_t   = sums[s2 * 4 + 2] / denom;
        const float inner_iou = 0.5f * iou_term + 0.5f * inner_t;  // (1-INNER_W), INNER_W
        const float box_loss  = 0.5f * iou_term + 0.5f * inner_iou;
        cls_total += cls_loss;
        box_total += box_loss;
    }
    cls_total = cls_total / 3.0f;
    box_total = box_total / 3.0f;
    const float total = 0.5f * cls_total + 7.5f * box_total;
    out[0] = total;
    out[1] = cls_total;
    out[2] = box_total;

    // reset for next graph replay (same thread -> ordered; visible at kernel end)
    #pragma unroll
    for (int i = 0; i < 12; i++) g_acc[i].v = 0.0f;
    __threadfence();
    g_count = 0;
}

extern "C" void kernel_launch(void* const* d_in, const int* in_sizes, int n_in,
                              void* d_out, int out_size) {
    const float* p3   = (const float*)d_in[0];
    const float* p4   = (const float*)d_in[1];
    const float* p5   = (const float*)d_in[2];
    const int*   tcls = (const int*)  d_in[3];
    const float* tbox = (const float*)d_in[4];
    float* out = (float*)d_out;

    det_loss_fused<<<NBLK, 64>>>(p3, p4, p5, tcls, tbox, out);
}